// round 17
// baseline (speedup 1.0000x reference)
#include <cuda_runtime.h>

// Problem constants
constexpr int kB = 512;   // batch
constexpr int kL = 128;   // seq len
constexpr int kD = 128;   // model dim
// H = 4 heads of 32
constexpr float LOG2E = 1.4426950408889634f;

// Scratch (device globals: allocation-free rule)
__device__ float    g_x [kB * kL * kD];               // residual stream, [b][t][d]
__device__ unsigned g_xn[kB * kL * kD];               // LN output, tf32 bit patterns
__device__ float    g_h [kB * kL * kD];               // raw scan output h
__device__ float    g_pre[(size_t)kL * kB * 4 * kD];  // gate preacts (i,f,o scaled by log2e)
__device__ unsigned g_Wt[2 * 4 * kD * kD];            // W -> tf32 (i,f,o rows pre-scaled)

typedef unsigned long long ull;

__device__ __forceinline__ float tanh_fast(float x) {
    float y; asm("tanh.approx.f32 %0,%1;" : "=f"(y) : "f"(x)); return y;
}
__device__ __forceinline__ float ex2_fast(float x) {
    float y; asm("ex2.approx.f32 %0,%1;" : "=f"(y) : "f"(x)); return y;
}
__device__ __forceinline__ unsigned to_tf32(float f) {
    unsigned u; asm("cvt.rna.tf32.f32 %0, %1;" : "=r"(u) : "f"(f)); return u;
}

__device__ __forceinline__ void cp_async16(unsigned smem, const void* gptr) {
    asm volatile("cp.async.cg.shared.global [%0], [%1], 16;" :: "r"(smem), "l"(gptr));
}
__device__ __forceinline__ void cp_commit() {
    asm volatile("cp.async.commit_group;");
}
template<int N>
__device__ __forceinline__ void cp_wait() {
    asm volatile("cp.async.wait_group %0;" :: "n"(N));
}

#define MMA_TF32(C0,C1,C2,C3, A0,A1,A2,A3, B0,B1)                              \
    asm volatile(                                                              \
        "mma.sync.aligned.m16n8k8.row.col.f32.tf32.tf32.f32 "                  \
        "{%0,%1,%2,%3}, {%4,%5,%6,%7}, {%8,%9}, {%0,%1,%2,%3};"                \
        : "+f"(C0), "+f"(C1), "+f"(C2), "+f"(C3)                               \
        : "r"(A0), "r"(A1), "r"(A2), "r"(A3), "r"(B0), "r"(B1))

// ---------------------------------------------------------------------------
// W -> tf32 pre-round; gates i,f,o (g != 2) pre-scaled by log2e.
// ---------------------------------------------------------------------------
__global__ void k_wcvt(const float* __restrict__ Wg) {
    int i = blockIdx.x * 256 + threadIdx.x;
    #pragma unroll
    for (int j = 0; j < 4; j++) {
        int e = i * 4 + j;
        int g = (e >> 14) & 3;                 // [l][g][128][128]
        float sc = (g == 2) ? 1.f : LOG2E;
        g_Wt[e] = to_tf32(__ldg(&Wg[e]) * sc);
    }
}

// ---------------------------------------------------------------------------
// Fused embedding gather + LayerNorm(layer0). One warp per row of 128.
// ---------------------------------------------------------------------------
__global__ void k_embed_ln(const int* __restrict__ ids, const float4* __restrict__ emb,
                           const float* __restrict__ w, const float* __restrict__ bb) {
    int t    = blockIdx.x * 256 + threadIdx.x;
    int row  = t >> 5;
    int lane = t & 31;
    int id   = __ldg(&ids[row]);
    float4 v = emb[(size_t)id * 32 + lane];
    ((float4*)g_x)[(size_t)row * 32 + lane] = v;
    float s = v.x + v.y + v.z + v.w;
    float q = v.x*v.x + v.y*v.y + v.z*v.z + v.w*v.w;
    #pragma unroll
    for (int o = 16; o; o >>= 1) {
        s += __shfl_xor_sync(0xffffffffu, s, o);
        q += __shfl_xor_sync(0xffffffffu, q, o);
    }
    float mu  = s * (1.f / 128.f);
    float var = fmaxf(q * (1.f / 128.f) - mu * mu, 0.f);
    float rs  = rsqrtf(var + 1e-5f);
    float4 wv = ((const float4*)w)[lane];
    float4 bv = ((const float4*)bb)[lane];
    uint4 o4;
    o4.x = to_tf32((v.x - mu) * rs * wv.x + bv.x);
    o4.y = to_tf32((v.y - mu) * rs * wv.y + bv.y);
    o4.z = to_tf32((v.z - mu) * rs * wv.z + bv.z);
    o4.w = to_tf32((v.w - mu) * rs * wv.w + bv.w);
    ((uint4*)g_xn)[(size_t)row * 32 + lane] = o4;
}

// ---------------------------------------------------------------------------
// Fused GroupNorm + residual (+ optional LayerNorm->tf32 for next layer).
// ---------------------------------------------------------------------------
template<bool DO_LN>
__global__ void k_gn(const float* __restrict__ gnw,
                     const float* __restrict__ lnw, const float* __restrict__ lnb) {
    const unsigned FULL = 0xffffffffu;
    int t    = blockIdx.x * 256 + threadIdx.x;
    int row  = t >> 5;
    int lane = t & 31;
    float4 hv = ((const float4*)g_h)[(size_t)row * 32 + lane];
    float4 xv = ((const float4*)g_x)[(size_t)row * 32 + lane];
    float s = hv.x + hv.y + hv.z + hv.w;
    float q = hv.x*hv.x + hv.y*hv.y + hv.z*hv.z + hv.w*hv.w;
    #pragma unroll
    for (int o = 1; o < 8; o <<= 1) {
        s += __shfl_xor_sync(FULL, s, o);
        q += __shfl_xor_sync(FULL, q, o);
    }
    float mu  = s * (1.f / 32.f);
    float var = fmaxf(q * (1.f / 32.f) - mu * mu, 0.f);
    float rs  = rsqrtf(var + 1e-5f);
    float4 gw = ((const float4*)gnw)[lane];
    float4 xp;
    xp.x = xv.x + (hv.x - mu) * rs * gw.x;
    xp.y = xv.y + (hv.y - mu) * rs * gw.y;
    xp.z = xv.z + (hv.z - mu) * rs * gw.z;
    xp.w = xv.w + (hv.w - mu) * rs * gw.w;
    ((float4*)g_x)[(size_t)row * 32 + lane] = xp;

    if (DO_LN) {
        float s2 = xp.x + xp.y + xp.z + xp.w;
        float q2 = xp.x*xp.x + xp.y*xp.y + xp.z*xp.z + xp.w*xp.w;
        #pragma unroll
        for (int o = 16; o; o >>= 1) {
            s2 += __shfl_xor_sync(FULL, s2, o);
            q2 += __shfl_xor_sync(FULL, q2, o);
        }
        float mu2  = s2 * (1.f / 128.f);
        float var2 = fmaxf(q2 * (1.f / 128.f) - mu2 * mu2, 0.f);
        float rs2  = rsqrtf(var2 + 1e-5f);
        float4 wv = ((const float4*)lnw)[lane];
        float4 bv = ((const float4*)lnb)[lane];
        uint4 o4;
        o4.x = to_tf32((xp.x - mu2) * rs2 * wv.x + bv.x);
        o4.y = to_tf32((xp.y - mu2) * rs2 * wv.y + bv.y);
        o4.z = to_tf32((xp.z - mu2) * rs2 * wv.z + bv.z);
        o4.w = to_tf32((xp.w - mu2) * rs2 * wv.w + bv.w);
        ((uint4*)g_xn)[(size_t)row * 32 + lane] = o4;
    }
}

// ---------------------------------------------------------------------------
// Persistent tf32 GEMM (round-15). grid (4, 74) = 296 CTAs = 2/SM, one wave.
// B (this gate's W, 64 KB) resident; A streamed in 16 KB K-chunks.
// ---------------------------------------------------------------------------
constexpr int GSTR = 36;
constexpr int GEMM_SMEM = 6 * 128 * GSTR * 4;   // 110592

__global__ void __launch_bounds__(256, 2) k_gemm(int layer,
                                                 const float* __restrict__ bias) {
    extern __shared__ unsigned sh[];
    unsigned* Bs  = sh;                          // [4][128][GSTR]
    unsigned* As0 = sh + 4 * 128 * GSTR;
    unsigned* As1 = As0 + 128 * GSTR;

    int tid = threadIdx.x;
    int bn  = blockIdx.x;                        // gate
    int by  = blockIdx.y;                        // 0..73
    int ntile = (585 - by) / 74;                 // 6 or 7 tiles
    int nchunk = ntile * 4;

    const unsigned* Wg = g_Wt + (size_t)(layer * 4 + bn) * 128 * 128;
    unsigned As_u[2] = { (unsigned)__cvta_generic_to_shared(As0),
                         (unsigned)__cvta_generic_to_shared(As1) };
    unsigned Bs_u = (unsigned)__cvta_generic_to_shared(Bs);

    auto issueA = [&](int gidx) {
        if (gidx < nchunk) {
            int bm = by + 74 * (gidx >> 2);
            int kc = gidx & 3;
            const unsigned* Ag = g_xn + (size_t)bm * 128 * 128;
            unsigned dst = As_u[gidx & 1];
            #pragma unroll
            for (int i = 0; i < 4; i++) {
                int e = i * 256 + tid, rr = e >> 3, cc = e & 7;
                cp_async16(dst + (rr * GSTR + cc * 4) * 4,
                           Ag + rr * 128 + kc * 32 + cc * 4);
            }
        }
        cp_commit();
    };

    #pragma unroll
    for (int kc = 0; kc < 4; kc++)
        #pragma unroll
        for (int i = 0; i < 4; i++) {
            int e = i * 256 + tid, rr = e >> 3, cc = e & 7;
            cp_async16(Bs_u + ((kc * 128 + rr) * GSTR + cc * 4) * 4,
                       Wg + rr * 128 + kc * 32 + cc * 4);
        }
    issueA(0);
    issueA(1);

    int warp = tid >> 5, lane = tid & 31;
    int wm = warp >> 2, wn = warp & 3;
    int gid = lane >> 2, tg = lane & 3;

    float bsc = (bn == 2) ? 1.f : LOG2E;
    float bz[4][2];
    #pragma unroll
    for (int j = 0; j < 4; j++) {
        int col = bn * 128 + wn * 32 + j * 8 + tg * 2;
        bz[j][0] = __ldg(&bias[col]) * bsc;
        bz[j][1] = __ldg(&bias[col + 1]) * bsc;
    }

    float acc[4][4][4];
    #pragma unroll
    for (int i = 0; i < 4; i++)
        #pragma unroll
        for (int j = 0; j < 4; j++) {
            acc[i][j][0] = bz[j][0]; acc[i][j][1] = bz[j][1];
            acc[i][j][2] = bz[j][0]; acc[i][j][3] = bz[j][1];
        }

    for (int g = 0; g < nchunk; g++) {
        int kc = g & 3;
        cp_wait<1>();
        __syncthreads();

        unsigned* As  = (g & 1) ? As1 : As0;
        unsigned* Bsk = Bs + kc * 128 * GSTR;

        #pragma unroll
        for (int ks = 0; ks < 4; ks++) {
            int k0 = ks * 8 + tg;
            unsigned a[4][4], bf[4][2];
            #pragma unroll
            for (int i = 0; i < 4; i++) {
                int r0 = wm * 64 + i * 16 + gid;
                a[i][0] = As[r0 * GSTR + k0];
                a[i][1] = As[(r0 + 8) * GSTR + k0];
                a[i][2] = As[r0 * GSTR + k0 + 4];
                a[i][3] = As[(r0 + 8) * GSTR + k0 + 4];
            }
            #pragma unroll
            for (int j = 0; j < 4; j++) {
                int n0 = wn * 32 + j * 8 + gid;
                bf[j][0] = Bsk[n0 * GSTR + k0];
                bf[j][1] = Bsk[n0 * GSTR + k0 + 4];
            }
            #pragma unroll
            for (int i = 0; i < 4; i++)
                #pragma unroll
                for (int j = 0; j < 4; j++)
                    MMA_TF32(acc[i][j][0], acc[i][j][1], acc[i][j][2], acc[i][j][3],
                             a[i][0], a[i][1], a[i][2], a[i][3],
                             bf[j][0], bf[j][1]);
        }
        __syncthreads();
        issueA(g + 2);

        if (kc == 3) {
            int bm = by + 74 * (g >> 2);
            #pragma unroll
            for (int i = 0; i < 4; i++) {
                int la = wm * 64 + i * 16 + gid;
                int lb = la + 8;
                float* outa = g_pre + ((size_t)la * 512 + bm) * 512;
                float* outb = g_pre + ((size_t)lb * 512 + bm) * 512;
                #pragma unroll
                for (int j = 0; j < 4; j++) {
                    int col = bn * 128 + wn * 32 + j * 8 + tg * 2;
                    *(float2*)&outa[col] = make_float2(acc[i][j][0], acc[i][j][1]);
                    *(float2*)&outb[col] = make_float2(acc[i][j][2], acc[i][j][3]);
                }
            }
            #pragma unroll
            for (int i = 0; i < 4; i++)
                #pragma unroll
                for (int j = 0; j < 4; j++) {
                    acc[i][j][0] = bz[j][0]; acc[i][j][1] = bz[j][1];
                    acc[i][j][2] = bz[j][0]; acc[i][j][3] = bz[j][1];
                }
        }
    }
}

// ---------------------------------------------------------------------------
// sLSTM gate math, log2 domain for i,f,o.
// ---------------------------------------------------------------------------
__device__ __forceinline__ void gate_step(float ai, float af, float az, float ao,
                                          float& h, float& c, float& n, float& m) {
    float fm = af + m;
    float mn = fmaxf(fm, ai);
    float iv = ex2_fast(ai - mn);
    float fv = ex2_fast(fm - mn);
    float th = tanh_fast(az);
    c = fmaf(fv, c, iv * th);
    n = fmaf(fv, n, iv);
    float eo = ex2_fast(-ao);
    float denom = fmaf(n, eo, n);
    h = __fdividef(c, denom);
    m = mn;
}

// ---------------------------------------------------------------------------
// Recurrent sLSTM scan, scalar-FFMA matvec (no f32x2 packing ALU).
// Grid 128 x 256, 4 batches/CTA, thread = (batch-pair, o), warp = head.
// h broadcast through SMEM (LDS.128 -> components feed FFMAs directly).
// Two accumulator sub-chains per gate (depth 16) to hide FFMA latency.
// R rows for gates i,f,o pre-scaled by log2e.
// ---------------------------------------------------------------------------
__global__ void __launch_bounds__(256, 1) k_scan(const float* __restrict__ R) {
    __shared__ float shA[2][2][4][32];        // [slot][grp][head][d]
    __shared__ float shB[2][2][4][32];

    int o    = threadIdx.x & 127;            // output dim
    int grp  = threadIdx.x >> 7;             // batch pair within CTA
    int hh   = (threadIdx.x >> 5) & 3;       // head
    int lane = threadIdx.x & 31;

    int b0 = blockIdx.x * 4 + grp * 2;       // batch A; batch B = b0+1

    // Rr[g*32 + d] = R[g][hh][d][lane] (scaled)
    float Rr[128];
    #pragma unroll
    for (int g = 0; g < 4; g++) {
        float sc = (g == 2) ? 1.f : LOG2E;
        #pragma unroll
        for (int d = 0; d < 32; d++)
            Rr[g * 32 + d] = __ldg(&R[((g * 4 + hh) * 32 + d) * 32 + lane]) * sc;
    }

    float hA = 0.f, cA = 0.f, nA = 0.f, mA = 0.f;
    float hB = 0.f, cB = 0.f, nB = 0.f, mB = 0.f;

    const float* pA = g_pre + (size_t)b0 * 512 + o;
    const float* pB = pA + 512;
    float* hoA = g_h + (size_t)b0 * kL * kD + o;
    float* hoB = hoA + (size_t)kL * kD;

    float a0 = pA[0], a1 = pA[128], a2 = pA[256], a3 = pA[384];
    float q0 = pB[0], q1 = pB[128], q2 = pB[256], q3 = pB[384];

    for (int t = 0; t < kL; t++) {
        int s = t & 1;
        shA[s][grp][hh][lane] = hA;
        shB[s][grp][hh][lane] = hB;
        __syncwarp();

        // two sub-chains per gate per batch; chain 0 seeded with pre
        float gA0[4] = {a0, a1, a2, a3};
        float gA1[4] = {0.f, 0.f, 0.f, 0.f};
        float gB0[4] = {q0, q1, q2, q3};
        float gB1[4] = {0.f, 0.f, 0.f, 0.f};

        if (t + 1 < kL) {
            const float* nA_ = pA + (size_t)(t + 1) * (kB * 512);
            const float* nB_ = pB + (size_t)(t + 1) * (kB * 512);
            a0 = nA_[0]; a1 = nA_[128]; a2 = nA_[256]; a3 = nA_[384];
            q0 = nB_[0]; q1 = nB_[128]; q2 = nB_[256]; q3 = nB_[384];
        }

        const float4* h4A = (const float4*)shA[s][grp][hh];
        const float4* h4B = (const float4*)shB[s][grp][hh];
        #pragma unroll
        for (int j = 0; j < 8; j++) {
            float4 va = h4A[j];
            float4 vb = h4B[j];
            int d = 4 * j;
            #pragma unroll
            for (int g = 0; g < 4; g++) {
                const float* Rg_ = Rr + g * 32 + d;
                gA0[g] = fmaf(va.x, Rg_[0], gA0[g]);
                gA1[g] = fmaf(va.y, Rg_[1], gA1[g]);
                gA0[g] = fmaf(va.z, Rg_[2], gA0[g]);
                gA1[g] = fmaf(va.w, Rg_[3], gA1[g]);
                gB0[g] = fmaf(vb.x, Rg_[0], gB0[g]);
                gB1[g] = fmaf(vb.y, Rg_[1], gB1[g]);
                gB0[g] = fmaf(vb.z, Rg_[2], gB0[g]);
                gB1[g] = fmaf(vb.w, Rg_[3], gB1[g]);
            }
        }

        gate_step(gA0[0] + gA1[0], gA0[1] + gA1[1],
                  gA0[2] + gA1[2], gA0[3] + gA1[3], hA, cA, nA, mA);
        gate_step(gB0[0] + gB1[0], gB0[1] + gB1[1],
                  gB0[2] + gB1[2], gB0[3] + gB1[3], hB, cB, nB, mB);

        hoA[(size_t)t * kD] = hA;
        hoB[(size_t)t * kD] = hB;
    }
}

// ---------------------------------------------------------------------------
// Head: mean over time, then 128->64 ReLU MLP, then 64->2
// ---------------------------------------------------------------------------
__global__ void k_head(const float* __restrict__ w1, const float* __restrict__ b1,
                       const float* __restrict__ w2, const float* __restrict__ b2,
                       float* __restrict__ out) {
    __shared__ float pooled[128];
    __shared__ float hid[64];
    int b = blockIdx.x, o = threadIdx.x;
    const float* xb = g_x + (size_t)b * kL * kD + o;
    float s = 0.f;
    #pragma unroll 8
    for (int t = 0; t < kL; t++) s += xb[(size_t)t * kD];
    pooled[o] = s * (1.f / 128.f);
    __syncthreads();
    if (o < 64) {
        float a = __ldg(&b1[o]);
        const float* wr = w1 + o * 128;
        #pragma unroll
        for (int d = 0; d < 128; d++) a = fmaf(pooled[d], __ldg(&wr[d]), a);
        hid[o] = fmaxf(a, 0.f);
    }
    __syncthreads();
    if (o < 2) {
        float a = __ldg(&b2[o]);
        const float* wr = w2 + o * 64;
        #pragma unroll
        for (int j = 0; j < 64; j++) a = fmaf(hid[j], __ldg(&wr[j]), a);
        out[b * 2 + o] = a;
    }
}

// ---------------------------------------------------------------------------
extern "C" void kernel_launch(void* const* d_in, const int* in_sizes, int n_in,
                              void* d_out, int out_size) {
    const int*   ids  = (const int*)  d_in[0];
    const float* emb  = (const float*)d_in[1];
    const float* ln_w = (const float*)d_in[2];
    const float* ln_b = (const float*)d_in[3];
    const float* Wg   = (const float*)d_in[4];
    const float* Rg   = (const float*)d_in[5];
    const float* bg   = (const float*)d_in[6];
    const float* gn_w = (const float*)d_in[7];
    const float* w1   = (const float*)d_in[8];
    const float* b1   = (const float*)d_in[9];
    const float* w2   = (const float*)d_in[10];
    const float* b2   = (const float*)d_in[11];
    float* out = (float*)d_out;

    cudaFuncSetAttribute(k_gemm, cudaFuncAttributeMaxDynamicSharedMemorySize, GEMM_SMEM);

    const int ROWS = kB * kL;                      // 65536 rows of 128

    k_wcvt<<<128, 256>>>(Wg);                      // both layers' W -> tf32 (scaled)
    k_embed_ln<<<ROWS / 8, 256>>>(ids, (const float4*)emb, ln_w, ln_b);

    // layer 0
    k_gemm<<<dim3(4, 74), 256, GEMM_SMEM>>>(0, bg);
    k_scan<<<128, 256>>>(Rg);
    k_gn<true><<<ROWS / 8, 256>>>(gn_w, ln_w + 128, ln_b + 128);

    // layer 1
    k_gemm<<<dim3(4, 74), 256, GEMM_SMEM>>>(1, bg + 512);
    k_scan<<<128, 256>>>(Rg + (size_t)4 * 4 * 32 * 32);
    k_gn<false><<<ROWS / 8, 256>>>(gn_w + 128, nullptr, nullptr);

    k_head<<<512, 128>>>(w1, b1, w2, b2, out);
}